// round 12
// baseline (speedup 1.0000x reference)
#include <cuda_runtime.h>
#include <cstdint>

#define TPB       256
#define TOK_CTA   512
#define TILE      128
#define NTILES    (TOK_CTA / TILE)   // 4
#define NMT       8                  // m-tiles (16 rows each)
#define NKT       4                  // k-tiles (k16 each) over DIM=64
#define NE        8
#define NH        64
#define GHD       32

// ---- dynamic smem layout (bytes, all 16B aligned) ----
#define OFF_XS    0                  // 32 grp * 33 uint4 = 16896
#define OFF_GH    16896              // 16 grp * 33 uint4 = 8448
#define OFF_RAW   25344              // 2 * 32768 raw floats
#define OFF_EO    90880              // 128*9 f = 4608
#define OFF_P     95488              // 128*9 f = 4608
#define OFF_SGF1  100096             // 8*32 uint2 = 2048
#define OFF_SGF2  102144             // 2*32 uint2 = 512
#define OFF_W2    102656             // 512 f
#define OFF_B1    104704             // 512 f
#define SMEM_BYTES 106752

__device__ __forceinline__ unsigned ph2(float a, float b) {
    unsigned r;
    asm("cvt.rn.f16x2.f32 %0, %2, %1;" : "=r"(r) : "f"(a), "f"(b));
    return r;
}
__device__ __forceinline__ void mma_f16(float* c,
                                        unsigned a0, unsigned a1, unsigned a2, unsigned a3,
                                        unsigned b0, unsigned b1) {
    asm volatile(
        "mma.sync.aligned.m16n8k16.row.col.f32.f16.f16.f32 "
        "{%0,%1,%2,%3}, {%4,%5,%6,%7}, {%8,%9}, {%0,%1,%2,%3};\n"
        : "+f"(c[0]), "+f"(c[1]), "+f"(c[2]), "+f"(c[3])
        : "r"(a0), "r"(a1), "r"(a2), "r"(a3), "r"(b0), "r"(b1));
}
__device__ __forceinline__ uint32_t smem_u32(const void* p) {
    uint32_t a;
    asm("{ .reg .u64 t; cvta.to.shared.u64 t, %1; cvt.u32.u64 %0, t; }" : "=r"(a) : "l"(p));
    return a;
}
__device__ __forceinline__ void cp16(uint32_t dst, const void* src) {
    asm volatile("{\n\t.reg .u64 g;\n\tcvta.to.global.u64 g, %1;\n\t"
                 "cp.async.ca.shared.global [%0], [g], 16;\n\t}"
                 :: "r"(dst), "l"(src) : "memory");
}
#define CP_COMMIT() asm volatile("cp.async.commit_group;" ::: "memory")
#define CP_WAIT0()  asm volatile("cp.async.wait_group 0;" ::: "memory")

__device__ __forceinline__ const float4* tok_src(const float* __restrict__ A,
                                                 const float* __restrict__ S,
                                                 int tb, int j) {
    const int t = j >> 4, dq = j & 15;
    return (dq < 8) ? ((const float4*)A) + ((size_t)(tb + t) * 8 + dq)
                    : ((const float4*)S) + ((size_t)(tb + t) * 8 + (dq - 8));
}

__global__ void __launch_bounds__(TPB, 2)
moe_f16_kernel(const float* __restrict__ A,  const float* __restrict__ S,
               const float* __restrict__ gw1, const float* __restrict__ gb1,
               const float* __restrict__ gw2, const float* __restrict__ gb2,
               const float* __restrict__ ew1, const float* __restrict__ eb1,
               const float* __restrict__ ew2, const float* __restrict__ eb2,
               float* __restrict__ out)
{
    extern __shared__ char sm[];
    uint4*    XSv  = (uint4*)(sm + OFF_XS);
    uint4*    GH4  = (uint4*)(sm + OFF_GH);
    float*    EO   = (float*)(sm + OFF_EO);
    float*    Pf   = (float*)(sm + OFF_P);
    uint2*    sgf1 = (uint2*)(sm + OFF_SGF1);
    uint2*    sgf2 = (uint2*)(sm + OFF_SGF2);
    float*    sw2  = (float*)(sm + OFF_W2);
    float*    sb1  = (float*)(sm + OFF_B1);
    const uint32_t smb = smem_u32(sm);

    const int tid  = threadIdx.x;
    const int w    = tid >> 5;              // warp id == expert id (0..7)
    const int lane = tid & 31;
    const int g    = lane >> 2;
    const int tig  = lane & 3;

    for (int i = tid; i < NE * NH; i += TPB) { sw2[i] = ew2[i]; sb1[i] = eb1[i]; }
    const float sb2e = eb2[w];

    // ---- expert B-fragments (fp16): 8 nt x 4 kt x 2 = 64 regs ----
    unsigned bf[8][4][2];
    {
        const float* we = ew1 + w * (64 * NH);
        #pragma unroll
        for (int nt = 0; nt < 8; nt++)
            #pragma unroll
            for (int kt = 0; kt < 4; kt++) {
                const int k0 = kt*16 + 2*tig;
                const int n  = nt*8 + g;
                bf[nt][kt][0] = ph2(we[k0*NH + n],     we[(k0+1)*NH + n]);
                bf[nt][kt][1] = ph2(we[(k0+8)*NH + n], we[(k0+9)*NH + n]);
            }
    }

    // ---- gating B-frags into smem; biases in regs ----
    float gba = 0.f, gbb = 0.f;
    if (w < 4) {
        #pragma unroll
        for (int kt = 0; kt < 2; kt++) {
            const int k0 = kt*16 + 2*tig;
            const int n  = w*8 + g;
            sgf1[(w*2+kt)*32 + lane] =
                make_uint2(ph2(gw1[k0*GHD + n],     gw1[(k0+1)*GHD + n]),
                           ph2(gw1[(k0+8)*GHD + n], gw1[(k0+9)*GHD + n]));
        }
        gba = gb1[w*8 + 2*tig];
        gbb = gb1[w*8 + 2*tig + 1];
    } else if (w == 4) {
        #pragma unroll
        for (int kt = 0; kt < 2; kt++) {
            const int k0 = kt*16 + 2*tig;
            sgf2[kt*32 + lane] =
                make_uint2(ph2(gw2[k0*NE + g],     gw2[(k0+1)*NE + g]),
                           ph2(gw2[(k0+8)*NE + g], gw2[(k0+9)*NE + g]));
        }
        gba = gb2[2*tig];
        gbb = gb2[2*tig + 1];
    }

    const int ctaBase = blockIdx.x * TOK_CTA;
    unsigned* XSw = (unsigned*)XSv;
    unsigned* GHw = (unsigned*)GH4;

    // ---- preload tile 0 raw into buffer 0 ----
    #pragma unroll
    for (int k = 0; k < 8; k++) {
        const int j = tid + k * TPB;
        cp16(smb + OFF_RAW + (uint32_t)j * 16, tok_src(A, S, ctaBase, j));
    }
    CP_COMMIT();
    CP_WAIT0();   // own slots; convert below reads exactly these

    #pragma unroll 1
    for (int it = 0; it < NTILES; it++) {
        const int p  = it & 1;
        const int tb = ctaBase + it * TILE;

        // ---- convert raw[p] -> fp16 A-fragments ----
        #pragma unroll
        for (int k = 0; k < 8; k++) {
            const int j = tid + k * TPB;         // 0..2047
            const float4 v = *(const float4*)(sm + OFF_RAW + p*32768 + j*16);
            const int t  = j >> 4, dq = j & 15;
            const int mt  = t >> 4, r = t & 15;
            const int kt  = dq >> 2, dk0 = (dq & 3) * 4;
            const int reg = (r >= 8 ? 1 : 0) + (dk0 >= 8 ? 2 : 0);
            const int l0  = (r & 7) * 4 + ((dk0 & 7) >> 1);
            const int wb  = (((mt*4 + kt)*33 + l0) << 2) + reg;
            XSw[wb]     = ph2(v.x, v.y);
            XSw[wb + 4] = ph2(v.z, v.w);
        }
        __syncthreads();   // XS ready

        // ---- prefetch next tile into raw[p^1] ----
        if (it + 1 < NTILES) {
            #pragma unroll
            for (int k = 0; k < 8; k++) {
                const int j = tid + k * TPB;
                cp16(smb + OFF_RAW + (uint32_t)((p^1)*32768 + j*16),
                     tok_src(A, S, tb + TILE, j));
            }
            CP_COMMIT();
        }

        // ---- gating (warps 0-4): uses S-half of X frags (kt 2,3) ----
        if (w < 4) {
            #pragma unroll
            for (int mt = 0; mt < NMT; mt++) {
                float ga[4] = {gba, gbb, gba, gbb};
                #pragma unroll
                for (int kt = 0; kt < 2; kt++) {
                    uint4 av = XSv[(mt*4 + 2 + kt)*33 + lane];
                    uint2 bv = sgf1[(w*2 + kt)*32 + lane];
                    mma_f16(ga, av.x, av.y, av.z, av.w, bv.x, bv.y);
                }
                const int kt2 = w >> 1;
                const int base = (((mt*2 + kt2)*33 + g*4 + tig) << 2) + 2*(w & 1);
                GHw[base]     = ph2(fmaxf(ga[0], 0.f), fmaxf(ga[1], 0.f));
                GHw[base + 1] = ph2(fmaxf(ga[2], 0.f), fmaxf(ga[3], 0.f));
            }
            asm volatile("bar.sync 1, 160;" ::: "memory");
        } else if (w == 4) {
            asm volatile("bar.sync 1, 160;" ::: "memory");
            #pragma unroll
            for (int mt = 0; mt < NMT; mt++) {
                float la[4] = {gba, gbb, gba, gbb};
                #pragma unroll
                for (int kt = 0; kt < 2; kt++) {
                    uint4 av = GH4[(mt*2 + kt)*33 + lane];
                    uint2 bv = sgf2[kt*32 + lane];
                    mma_f16(la, av.x, av.y, av.z, av.w, bv.x, bv.y);
                }
                const int r = mt*16 + g;
                float m0 = fmaxf(la[0], la[1]);
                m0 = fmaxf(m0, __shfl_xor_sync(0xffffffffu, m0, 1));
                m0 = fmaxf(m0, __shfl_xor_sync(0xffffffffu, m0, 2));
                float e0 = __expf(la[0] - m0), e1 = __expf(la[1] - m0);
                float s0 = e0 + e1;
                s0 += __shfl_xor_sync(0xffffffffu, s0, 1);
                s0 += __shfl_xor_sync(0xffffffffu, s0, 2);
                float inv0 = 1.f / s0;
                Pf[r*9 + 2*tig    ] = e0 * inv0;
                Pf[r*9 + 2*tig + 1] = e1 * inv0;
                float m1 = fmaxf(la[2], la[3]);
                m1 = fmaxf(m1, __shfl_xor_sync(0xffffffffu, m1, 1));
                m1 = fmaxf(m1, __shfl_xor_sync(0xffffffffu, m1, 2));
                float e2 = __expf(la[2] - m1), e3 = __expf(la[3] - m1);
                float s1 = e2 + e3;
                s1 += __shfl_xor_sync(0xffffffffu, s1, 1);
                s1 += __shfl_xor_sync(0xffffffffu, s1, 2);
                float inv1 = 1.f / s1;
                Pf[(r+8)*9 + 2*tig    ] = e2 * inv1;
                Pf[(r+8)*9 + 2*tig + 1] = e3 * inv1;
            }
        }

        // ---- expert GEMM + epilogue (warp = full expert) ----
        #pragma unroll 1
        for (int mt = 0; mt < NMT; mt++) {
            float acc[8][4];
            #pragma unroll
            for (int nt = 0; nt < 8; nt++) {
                const float2 bv = *(const float2*)(sb1 + w*NH + nt*8 + 2*tig);
                acc[nt][0] = bv.x; acc[nt][1] = bv.y;
                acc[nt][2] = bv.x; acc[nt][3] = bv.y;
            }
            #pragma unroll
            for (int kt = 0; kt < NKT; kt++) {
                uint4 av = XSv[(mt*4 + kt)*33 + lane];
                #pragma unroll
                for (int nt = 0; nt < 8; nt++)
                    mma_f16(acc[nt], av.x, av.y, av.z, av.w,
                            bf[nt][kt][0], bf[nt][kt][1]);
            }
            float pg = 0.f, ph = 0.f;
            #pragma unroll
            for (int nt = 0; nt < 8; nt++) {
                const float2 wv = *(const float2*)(sw2 + w*NH + nt*8 + 2*tig);
                pg = fmaf(fmaxf(acc[nt][0], 0.f), wv.x, pg);
                pg = fmaf(fmaxf(acc[nt][1], 0.f), wv.y, pg);
                ph = fmaf(fmaxf(acc[nt][2], 0.f), wv.x, ph);
                ph = fmaf(fmaxf(acc[nt][3], 0.f), wv.y, ph);
            }
            pg += __shfl_xor_sync(0xffffffffu, pg, 1);
            pg += __shfl_xor_sync(0xffffffffu, pg, 2);
            ph += __shfl_xor_sync(0xffffffffu, ph, 1);
            ph += __shfl_xor_sync(0xffffffffu, ph, 2);
            if (tig == 0) {
                const int r = mt*16 + g;
                EO[r*9 + w]     = pg + sb2e;
                EO[(r+8)*9 + w] = ph + sb2e;
            }
        }

        __syncthreads();   // EO + Pf ready; XS free for next convert

        // ---- combine ----
        if (tid < TILE) {
            float a = 0.f;
            #pragma unroll
            for (int ee = 0; ee < NE; ee++)
                a = fmaf(Pf[tid*9 + ee], EO[tid*9 + ee], a);
            out[tb + tid] = a;
        }

        if (it + 1 < NTILES) CP_WAIT0();   // own raw[p^1] slots visible
    }
}

extern "C" void kernel_launch(void* const* d_in, const int* in_sizes, int n_in,
                              void* d_out, int out_size)
{
    const float* A   = (const float*)d_in[0];
    const float* S   = (const float*)d_in[1];
    const float* gw1 = (const float*)d_in[2];
    const float* gb1 = (const float*)d_in[3];
    const float* gw2 = (const float*)d_in[4];
    const float* gb2 = (const float*)d_in[5];
    const float* ew1 = (const float*)d_in[6];
    const float* eb1 = (const float*)d_in[7];
    const float* ew2 = (const float*)d_in[8];
    const float* eb2 = (const float*)d_in[9];
    float* out = (float*)d_out;

    cudaFuncSetAttribute(moe_f16_kernel,
                         cudaFuncAttributeMaxDynamicSharedMemorySize, SMEM_BYTES);

    const int b = in_sizes[0] / 32;          // 524288 tokens
    moe_f16_kernel<<<b / TOK_CTA, TPB, SMEM_BYTES>>>(A, S, gw1, gb1, gw2, gb2,
                                                     ew1, eb1, ew2, eb2, out);
}